// round 9
// baseline (speedup 1.0000x reference)
#include <cuda_runtime.h>
#include <math.h>
#include <stdint.h>

// ---------------------------------------------------------------------------
// out = tanh( adj @ (X @ Wn^T) + X @ Ws^T ),  N=10000, feature dim 128
//
// Refactor: Y = X@Wn^T, Z = X@Ws^T (tiny), then out = tanh(adj@Y + Z).
// Precision plan (tf32 mma with fp32 accuracy where it matters):
//   adj@Y = (adj-0.5)@Y + 0.5*colsum(Y)
//   A side: register split  a-0.5 = a_hi(tf32,rna) + a_lo   -> 2 mma passes
//   B side: Y pre-rounded to tf32 with rna; colsum from exact Y
// ---------------------------------------------------------------------------

#define NODE_CAP 10016
__device__ float g_Y[NODE_CAP * 128];
__device__ float g_Z[NODE_CAP * 128];
__device__ float g_S[128];            // colsum of exact Y

// ============================ helpers ======================================
__device__ __forceinline__ unsigned rna_tf32(float v)
{
    unsigned b;
    asm("cvt.rna.tf32.f32 %0, %1;" : "=r"(b) : "f"(v));
    return b;
}

__device__ __forceinline__ void split_tf32(float v, unsigned& hi, unsigned& lo)
{
    float ap = v - 0.5f;                 // center adj
    unsigned h = rna_tf32(ap);
    hi = h;
    lo = __float_as_uint(ap - __uint_as_float(h));   // residual (truncation ok)
}

// ============================ Phase 0: zero colsum =========================
__global__ void zero_kernel() { g_S[threadIdx.x] = 0.f; }

// ============================ Phase 1 ======================================
// grid (ceil(N/64), 4), block 256. blockIdx.y: 0,1 -> Y (Wn), 2,3 -> Z (Ws).
__global__ void __launch_bounds__(256) phase1_kernel(
    const float* __restrict__ X, const float* __restrict__ Wn,
    const float* __restrict__ Ws, int N)
{
    __shared__ float As[64][64];   // As[k][m]
    __shared__ float Bs[64][64];   // Bs[k][n]
    const int tid = threadIdx.x;
    const int tx = tid & 15, ty = tid >> 4;
    const int m0 = blockIdx.x * 64;
    const int nb = blockIdx.y;
    const float* __restrict__ W = (nb < 2) ? Wn : Ws;
    const int n0 = (nb & 1) * 64;

    float acc[4][4];
#pragma unroll
    for (int i = 0; i < 4; i++)
#pragma unroll
        for (int j = 0; j < 4; j++) acc[i][j] = 0.f;

    for (int kt = 0; kt < 2; kt++) {
        __syncthreads();
#pragma unroll
        for (int it = 0; it < 4; it++) {
            int e = tid + it * 256;
            int m = e & 63, kq = e >> 6;          // kq: 0..15 (float4 index)
            float4 v = make_float4(0.f, 0.f, 0.f, 0.f);
            if (m0 + m < N)
                v = *(const float4*)&X[(size_t)(m0 + m) * 128 + kt * 64 + kq * 4];
            As[kq * 4 + 0][m] = v.x; As[kq * 4 + 1][m] = v.y;
            As[kq * 4 + 2][m] = v.z; As[kq * 4 + 3][m] = v.w;
            float4 w = *(const float4*)&W[(size_t)(n0 + m) * 128 + kt * 64 + kq * 4];
            Bs[kq * 4 + 0][m] = w.x; Bs[kq * 4 + 1][m] = w.y;
            Bs[kq * 4 + 2][m] = w.z; Bs[kq * 4 + 3][m] = w.w;
        }
        __syncthreads();
#pragma unroll 8
        for (int k = 0; k < 64; k++) {
            float4 a = *(const float4*)&As[k][ty * 4];
            float4 b = *(const float4*)&Bs[k][tx * 4];
            acc[0][0] += a.x * b.x; acc[0][1] += a.x * b.y; acc[0][2] += a.x * b.z; acc[0][3] += a.x * b.w;
            acc[1][0] += a.y * b.x; acc[1][1] += a.y * b.y; acc[1][2] += a.y * b.z; acc[1][3] += a.y * b.w;
            acc[2][0] += a.z * b.x; acc[2][1] += a.z * b.y; acc[2][2] += a.z * b.z; acc[2][3] += a.z * b.w;
            acc[3][0] += a.w * b.x; acc[3][1] += a.w * b.y; acc[3][2] += a.w * b.z; acc[3][3] += a.w * b.w;
        }
    }

    float* __restrict__ dst = (nb < 2) ? g_Y : g_Z;
    const int colg = (nb & 1) * 64 + tx * 4;
#pragma unroll
    for (int i = 0; i < 4; i++) {
        int r = m0 + ty * 4 + i;
        if (r < N) {
            float4 o = make_float4(acc[i][0], acc[i][1], acc[i][2], acc[i][3]);
            *(float4*)&dst[(size_t)r * 128 + colg] = o;
        }
    }
}

// ============================ Phase 1b: colsum + round Y ===================
// grid ceil(N/128), block 256. Sums exact Y per column into g_S, then
// rounds g_Y to tf32 (rna) in place.
__global__ void __launch_bounds__(256) prep_kernel(int N)
{
    __shared__ float red[256];
    const int tid = threadIdx.x;
    const int c = tid & 127;
    const int h = tid >> 7;
    const int r0 = blockIdx.x * 128;

    float local = 0.f;
    for (int r = h; r < 128; r += 2) {
        int row = r0 + r;
        if (row < N) {
            float* p = &g_Y[(size_t)row * 128 + c];
            float v = *p;
            local += v;
            *p = __uint_as_float(rna_tf32(v));
        }
    }
    red[tid] = local;
    __syncthreads();
    if (tid < 128) atomicAdd(&g_S[c], red[tid] + red[tid + 128]);
}

// ============================ Phase 2 ======================================
#define KC 32
#define STAGES 4
#define A_LD 36     // frag lds bank = (4r+c)%32 -> conflict-free
#define B_LD 136    // frag lds bank = (8k+n)%32 -> conflict-free
#define A_STAGE (64 * A_LD)
#define B_STAGE (32 * B_LD)

__device__ __forceinline__ void cp16(float* smem_dst, const float* gsrc, bool pred)
{
    unsigned sa = (unsigned)__cvta_generic_to_shared(smem_dst);
    int sz = pred ? 16 : 0;
    asm volatile("cp.async.cg.shared.global [%0], [%1], 16, %2;\n"
                 :: "r"(sa), "l"(gsrc), "r"(sz));
}

__device__ __forceinline__ void issue_chunk(
    float* sA, float* sB, const float* __restrict__ adj,
    const float* __restrict__ Y, int m0, int k0, int N, int tid)
{
    // A tile: 64 rows x 32 cols = 512 float4
#pragma unroll
    for (int it = 0; it < 2; it++) {
        int e = tid + it * 256;
        int row = e >> 3, kq = e & 7;
        int gr = m0 + row, gc = k0 + kq * 4;
        bool p = (gr < N) && (gc < N);
        const float* src = adj + (size_t)(p ? gr : 0) * (size_t)N + (p ? gc : 0);
        cp16(&sA[row * A_LD + kq * 4], src, p);
    }
    // B tile: 32 rows x 128 cols = 1024 float4  (ROUND-5 BUG FIX: full width)
#pragma unroll
    for (int it = 0; it < 4; it++) {
        int e = tid + it * 256;            // 0..1023
        int row = e >> 5;                  // 0..31
        int kq = e & 31;                   // 0..31 float4 -> 128 floats
        int gr = k0 + row;
        bool p = (gr < N);
        const float* src = Y + (size_t)(p ? gr : 0) * 128 + kq * 4;
        cp16(&sB[row * B_LD + kq * 4], src, p);
    }
    asm volatile("cp.async.commit_group;\n" ::);
}

__device__ __forceinline__ void mma_tf32(float* c, const unsigned* a, const unsigned* b)
{
    asm volatile(
        "mma.sync.aligned.m16n8k8.row.col.f32.tf32.tf32.f32 "
        "{%0,%1,%2,%3},{%4,%5,%6,%7},{%8,%9},{%0,%1,%2,%3};\n"
        : "+f"(c[0]), "+f"(c[1]), "+f"(c[2]), "+f"(c[3])
        : "r"(a[0]), "r"(a[1]), "r"(a[2]), "r"(a[3]), "r"(b[0]), "r"(b[1]));
}

__global__ void __launch_bounds__(256) phase2_kernel(
    const float* __restrict__ adj, float* __restrict__ out, int N)
{
    extern __shared__ float smem[];
    float* sAb = smem;
    float* sBb = smem + STAGES * A_STAGE;

    const int tid = threadIdx.x;
    const int lane = tid & 31;
    const int warp = tid >> 5;
    const int wm = warp & 1;   // 0..1 -> 32-row tile
    const int wn = warp >> 1;  // 0..3 -> 32-col tile
    const int m0 = blockIdx.x * 64;

    float acc[2][4][4];
#pragma unroll
    for (int i = 0; i < 2; i++)
#pragma unroll
        for (int j = 0; j < 4; j++)
#pragma unroll
            for (int k = 0; k < 4; k++) acc[i][j][k] = 0.f;

    const int NC = (N + KC - 1) / KC;

    for (int c = 0; c < STAGES - 1 && c < NC; c++)
        issue_chunk(sAb + (c % STAGES) * A_STAGE, sBb + (c % STAGES) * B_STAGE,
                    adj, g_Y, m0, c * KC, N, tid);

    for (int c = 0; c < NC; c++) {
        asm volatile("cp.async.wait_group %0;\n" :: "n"(STAGES - 2));
        __syncthreads();

        int nc_ = c + STAGES - 1;
        if (nc_ < NC)
            issue_chunk(sAb + (nc_ % STAGES) * A_STAGE, sBb + (nc_ % STAGES) * B_STAGE,
                        adj, g_Y, m0, nc_ * KC, N, tid);
        else
            asm volatile("cp.async.commit_group;\n" ::);

        const float* A = sAb + (c % STAGES) * A_STAGE;
        const float* B = sBb + (c % STAGES) * B_STAGE;

#pragma unroll
        for (int ks = 0; ks < 4; ks++) {
            unsigned ahi[2][4], alo[2][4], b[4][2];
#pragma unroll
            for (int im = 0; im < 2; im++) {
                int r = wm * 32 + im * 16 + (lane >> 2);
                int cc = ks * 8 + (lane & 3);
                float v0 = A[r * A_LD + cc];
                float v1 = A[(r + 8) * A_LD + cc];
                float v2 = A[r * A_LD + cc + 4];
                float v3 = A[(r + 8) * A_LD + cc + 4];
                split_tf32(v0, ahi[im][0], alo[im][0]);
                split_tf32(v1, ahi[im][1], alo[im][1]);
                split_tf32(v2, ahi[im][2], alo[im][2]);
                split_tf32(v3, ahi[im][3], alo[im][3]);
            }
#pragma unroll
            for (int jn = 0; jn < 4; jn++) {
                int col = wn * 32 + jn * 8 + (lane >> 2);
                int rr = ks * 8 + (lane & 3);
                b[jn][0] = __float_as_uint(B[rr * B_LD + col]);        // pre-rounded tf32
                b[jn][1] = __float_as_uint(B[(rr + 4) * B_LD + col]);
            }
#pragma unroll
            for (int im = 0; im < 2; im++)
#pragma unroll
                for (int jn = 0; jn < 4; jn++) {
                    mma_tf32(acc[im][jn], ahi[im], b[jn]);   // hi pass
                    mma_tf32(acc[im][jn], alo[im], b[jn]);   // lo pass
                }
        }
    }

    // epilogue: out = tanh(acc + Z + 0.5*colsumY)
    const int mr = m0 + wm * 32;
    const int nc0 = wn * 32;
#pragma unroll
    for (int im = 0; im < 2; im++)
#pragma unroll
        for (int jn = 0; jn < 4; jn++) {
            int cc = nc0 + jn * 8 + 2 * (lane & 3);
            float s0 = 0.5f * g_S[cc];
            float s1 = 0.5f * g_S[cc + 1];
            int r0 = mr + im * 16 + (lane >> 2);
            if (r0 < N) {
                float2 z = *(const float2*)&g_Z[(size_t)r0 * 128 + cc];
                float2 o = make_float2(tanhf(acc[im][jn][0] + z.x + s0),
                                       tanhf(acc[im][jn][1] + z.y + s1));
                *(float2*)&out[(size_t)r0 * 128 + cc] = o;
            }
            int r1 = r0 + 8;
            if (r1 < N) {
                float2 z = *(const float2*)&g_Z[(size_t)r1 * 128 + cc];
                float2 o = make_float2(tanhf(acc[im][jn][2] + z.x + s0),
                                       tanhf(acc[im][jn][3] + z.y + s1));
                *(float2*)&out[(size_t)r1 * 128 + cc] = o;
            }
        }
}

// ============================ Launch =======================================
extern "C" void kernel_launch(void* const* d_in, const int* in_sizes, int n_in,
                              void* d_out, int out_size)
{
    const float* adj = (const float*)d_in[0];
    const float* X   = (const float*)d_in[1];
    const float* Wn  = (const float*)d_in[2];
    const float* Ws  = (const float*)d_in[3];
    float* out = (float*)d_out;

    int N = in_sizes[1] / 128;      // 10000
    if (N > NODE_CAP) N = NODE_CAP;

    int mblocks64 = (N + 63) / 64;
    int mblocks128 = (N + 127) / 128;

    zero_kernel<<<1, 128>>>();
    phase1_kernel<<<dim3(mblocks64, 4), 256>>>(X, Wn, Ws, N);
    prep_kernel<<<mblocks128, 256>>>(N);

    int smem_bytes = STAGES * (A_STAGE + B_STAGE) * (int)sizeof(float); // 106496
    cudaFuncSetAttribute(phase2_kernel,
                         cudaFuncAttributeMaxDynamicSharedMemorySize, smem_bytes);
    phase2_kernel<<<mblocks64, 256, smem_bytes>>>(adj, out, N);
}

// round 10
// speedup vs baseline: 1.5727x; 1.5727x over previous
#include <cuda_runtime.h>
#include <math.h>
#include <stdint.h>

// ---------------------------------------------------------------------------
// out = tanh( adj @ (X @ Wn^T) + X @ Ws^T ),  N=10000, feature dim 128
//
// Y = X@Wn^T, Z = X@Ws^T (tiny), then out = tanh(adj@Y + Z).
// Precision (tf32 mma with fp32-grade accuracy):
//   adj@Y = (adj-0.5)@Y + 0.5*colsum(Y)
//   A side: register split  a-0.5 = a_hi(tf32,rna) + a_lo -> 2 mma passes
//   B side: Y rounded to tf32 (rna) in phase1; colsum from exact Y
// R9: split-K x3 for occupancy (1 -> 3 CTAs/SM), STAGES 4 -> 2,
//     fp32 partials + reduce kernel, colsum/rounding fused into phase1.
// ---------------------------------------------------------------------------

#define NODE_CAP 10016
#define SPLITS 3
__device__ float g_Y[NODE_CAP * 128];
__device__ float g_Z[NODE_CAP * 128];
__device__ float g_S[128];                         // colsum of exact Y
__device__ float g_P[SPLITS][NODE_CAP * 128];      // split-K partials

// ============================ helpers ======================================
__device__ __forceinline__ unsigned rna_tf32(float v)
{
    unsigned b;
    asm("cvt.rna.tf32.f32 %0, %1;" : "=r"(b) : "f"(v));
    return b;
}

__device__ __forceinline__ void split_tf32(float v, unsigned& hi, unsigned& lo)
{
    float ap = v - 0.5f;                 // center adj
    unsigned h = rna_tf32(ap);
    hi = h;
    lo = __float_as_uint(ap - __uint_as_float(h));   // residual
}

// ============================ Phase 0: zero colsum =========================
__global__ void zero_kernel() { g_S[threadIdx.x] = 0.f; }

// ============================ Phase 1 ======================================
// grid (ceil(N/64), 4), block 256. blockIdx.y: 0,1 -> Y (Wn), 2,3 -> Z (Ws).
// For Y blocks: stores tf32-rna-rounded Y, and atomically accumulates the
// exact column sums into g_S.
__global__ void __launch_bounds__(256) phase1_kernel(
    const float* __restrict__ X, const float* __restrict__ Wn,
    const float* __restrict__ Ws, int N)
{
    __shared__ float As[64][64];   // As[k][m]
    __shared__ float Bs[64][64];   // Bs[k][n]
    const int tid = threadIdx.x;
    const int tx = tid & 15, ty = tid >> 4;
    const int m0 = blockIdx.x * 64;
    const int nb = blockIdx.y;
    const float* __restrict__ W = (nb < 2) ? Wn : Ws;
    const int n0 = (nb & 1) * 64;

    float acc[4][4];
#pragma unroll
    for (int i = 0; i < 4; i++)
#pragma unroll
        for (int j = 0; j < 4; j++) acc[i][j] = 0.f;

    for (int kt = 0; kt < 2; kt++) {
        __syncthreads();
#pragma unroll
        for (int it = 0; it < 4; it++) {
            int e = tid + it * 256;
            int m = e & 63, kq = e >> 6;          // kq: 0..15 (float4 index)
            float4 v = make_float4(0.f, 0.f, 0.f, 0.f);
            if (m0 + m < N)
                v = *(const float4*)&X[(size_t)(m0 + m) * 128 + kt * 64 + kq * 4];
            As[kq * 4 + 0][m] = v.x; As[kq * 4 + 1][m] = v.y;
            As[kq * 4 + 2][m] = v.z; As[kq * 4 + 3][m] = v.w;
            float4 w = *(const float4*)&W[(size_t)(n0 + m) * 128 + kt * 64 + kq * 4];
            Bs[kq * 4 + 0][m] = w.x; Bs[kq * 4 + 1][m] = w.y;
            Bs[kq * 4 + 2][m] = w.z; Bs[kq * 4 + 3][m] = w.w;
        }
        __syncthreads();
#pragma unroll 8
        for (int k = 0; k < 64; k++) {
            float4 a = *(const float4*)&As[k][ty * 4];
            float4 b = *(const float4*)&Bs[k][tx * 4];
            acc[0][0] += a.x * b.x; acc[0][1] += a.x * b.y; acc[0][2] += a.x * b.z; acc[0][3] += a.x * b.w;
            acc[1][0] += a.y * b.x; acc[1][1] += a.y * b.y; acc[1][2] += a.y * b.z; acc[1][3] += a.y * b.w;
            acc[2][0] += a.z * b.x; acc[2][1] += a.z * b.y; acc[2][2] += a.z * b.z; acc[2][3] += a.z * b.w;
            acc[3][0] += a.w * b.x; acc[3][1] += a.w * b.y; acc[3][2] += a.w * b.z; acc[3][3] += a.w * b.w;
        }
    }

    const bool isY = (nb < 2);
    float* __restrict__ dst = isY ? g_Y : g_Z;
    const int colg = (nb & 1) * 64 + tx * 4;
    float csum[4] = {0.f, 0.f, 0.f, 0.f};
#pragma unroll
    for (int i = 0; i < 4; i++) {
        int r = m0 + ty * 4 + i;
        if (r < N) {
            float4 o;
            if (isY) {
#pragma unroll
                for (int j = 0; j < 4; j++) csum[j] += acc[i][j];
                o = make_float4(__uint_as_float(rna_tf32(acc[i][0])),
                                __uint_as_float(rna_tf32(acc[i][1])),
                                __uint_as_float(rna_tf32(acc[i][2])),
                                __uint_as_float(rna_tf32(acc[i][3])));
            } else {
                o = make_float4(acc[i][0], acc[i][1], acc[i][2], acc[i][3]);
            }
            *(float4*)&dst[(size_t)r * 128 + colg] = o;
        }
    }

    if (isY) {
        __syncthreads();                 // done reading As in k-loop
        float* red = &As[0][0];          // reuse as [16][64]
#pragma unroll
        for (int j = 0; j < 4; j++) red[ty * 64 + tx * 4 + j] = csum[j];
        __syncthreads();
        if (tid < 64) {
            float s = 0.f;
#pragma unroll
            for (int t = 0; t < 16; t++) s += red[t * 64 + tid];
            atomicAdd(&g_S[(nb & 1) * 64 + tid], s);
        }
    }
}

// ============================ Phase 2 ======================================
#define KC 32
#define STAGES 2
#define A_LD 36     // frag lds bank = (4r+c)%32 -> conflict-free
#define B_LD 136    // frag lds bank = (8k+n)%32 -> conflict-free
#define A_STAGE (64 * A_LD)
#define B_STAGE (32 * B_LD)

__device__ __forceinline__ void cp16(float* smem_dst, const float* gsrc, bool pred)
{
    unsigned sa = (unsigned)__cvta_generic_to_shared(smem_dst);
    int sz = pred ? 16 : 0;
    asm volatile("cp.async.cg.shared.global [%0], [%1], 16, %2;\n"
                 :: "r"(sa), "l"(gsrc), "r"(sz));
}

__device__ __forceinline__ void issue_chunk(
    float* sA, float* sB, const float* __restrict__ adj,
    const float* __restrict__ Y, int m0, int k0, int N, int tid)
{
    // A tile: 64 rows x 32 cols = 512 float4
#pragma unroll
    for (int it = 0; it < 2; it++) {
        int e = tid + it * 256;
        int row = e >> 3, kq = e & 7;
        int gr = m0 + row, gc = k0 + kq * 4;
        bool p = (gr < N) && (gc < N);
        const float* src = adj + (size_t)(p ? gr : 0) * (size_t)N + (p ? gc : 0);
        cp16(&sA[row * A_LD + kq * 4], src, p);
    }
    // B tile: 32 rows x 128 cols = 1024 float4
#pragma unroll
    for (int it = 0; it < 4; it++) {
        int e = tid + it * 256;
        int row = e >> 5;                  // 0..31
        int kq = e & 31;                   // 0..31 float4
        int gr = k0 + row;
        bool p = (gr < N);
        const float* src = Y + (size_t)(p ? gr : 0) * 128 + kq * 4;
        cp16(&sB[row * B_LD + kq * 4], src, p);
    }
    asm volatile("cp.async.commit_group;\n" ::);
}

__device__ __forceinline__ void mma_tf32(float* c, const unsigned* a, const unsigned* b)
{
    asm volatile(
        "mma.sync.aligned.m16n8k8.row.col.f32.tf32.tf32.f32 "
        "{%0,%1,%2,%3},{%4,%5,%6,%7},{%8,%9},{%0,%1,%2,%3};\n"
        : "+f"(c[0]), "+f"(c[1]), "+f"(c[2]), "+f"(c[3])
        : "r"(a[0]), "r"(a[1]), "r"(a[2]), "r"(a[3]), "r"(b[0]), "r"(b[1]));
}

// grid (ceil(N/64), SPLITS), block 256. Each (x,y) CTA computes the partial
// (adj-0.5)[64 rows, k-range] @ Y and writes fp32 partials to g_P[y].
__global__ void __launch_bounds__(256, 3) phase2_kernel(
    const float* __restrict__ adj, int N)
{
    extern __shared__ float smem[];
    float* sAb = smem;
    float* sBb = smem + STAGES * A_STAGE;

    const int tid = threadIdx.x;
    const int lane = tid & 31;
    const int warp = tid >> 5;
    const int wm = warp & 1;   // 0..1 -> 32-row tile
    const int wn = warp >> 1;  // 0..3 -> 32-col tile
    const int m0 = blockIdx.x * 64;
    const int split = blockIdx.y;

    float acc[2][4][4];
#pragma unroll
    for (int i = 0; i < 2; i++)
#pragma unroll
        for (int j = 0; j < 4; j++)
#pragma unroll
            for (int k = 0; k < 4; k++) acc[i][j][k] = 0.f;

    const int NCtot = (N + KC - 1) / KC;
    const int per = (NCtot + SPLITS - 1) / SPLITS;
    const int c_begin = split * per;
    const int c_end = min(NCtot, c_begin + per);

    for (int c = c_begin; c < c_begin + (STAGES - 1) && c < c_end; c++)
        issue_chunk(sAb + (c % STAGES) * A_STAGE, sBb + (c % STAGES) * B_STAGE,
                    adj, g_Y, m0, c * KC, N, tid);

    for (int c = c_begin; c < c_end; c++) {
        asm volatile("cp.async.wait_group %0;\n" :: "n"(STAGES - 2));
        __syncthreads();

        int nc_ = c + STAGES - 1;
        if (nc_ < c_end)
            issue_chunk(sAb + (nc_ % STAGES) * A_STAGE, sBb + (nc_ % STAGES) * B_STAGE,
                        adj, g_Y, m0, nc_ * KC, N, tid);
        else
            asm volatile("cp.async.commit_group;\n" ::);

        const float* A = sAb + (c % STAGES) * A_STAGE;
        const float* B = sBb + (c % STAGES) * B_STAGE;

#pragma unroll
        for (int ks = 0; ks < 4; ks++) {
            unsigned ahi[2][4], alo[2][4], b[4][2];
#pragma unroll
            for (int im = 0; im < 2; im++) {
                int r = wm * 32 + im * 16 + (lane >> 2);
                int cc = ks * 8 + (lane & 3);
                float v0 = A[r * A_LD + cc];
                float v1 = A[(r + 8) * A_LD + cc];
                float v2 = A[r * A_LD + cc + 4];
                float v3 = A[(r + 8) * A_LD + cc + 4];
                split_tf32(v0, ahi[im][0], alo[im][0]);
                split_tf32(v1, ahi[im][1], alo[im][1]);
                split_tf32(v2, ahi[im][2], alo[im][2]);
                split_tf32(v3, ahi[im][3], alo[im][3]);
            }
#pragma unroll
            for (int jn = 0; jn < 4; jn++) {
                int col = wn * 32 + jn * 8 + (lane >> 2);
                int rr = ks * 8 + (lane & 3);
                b[jn][0] = __float_as_uint(B[rr * B_LD + col]);   // pre-rounded tf32
                b[jn][1] = __float_as_uint(B[(rr + 4) * B_LD + col]);
            }
#pragma unroll
            for (int im = 0; im < 2; im++)
#pragma unroll
                for (int jn = 0; jn < 4; jn++) {
                    mma_tf32(acc[im][jn], ahi[im], b[jn]);   // hi pass
                    mma_tf32(acc[im][jn], alo[im], b[jn]);   // lo pass
                }
        }
    }

    // store fp32 partials (no tanh/Z here)
    float* __restrict__ P = g_P[split];
    const int mr = m0 + wm * 32;
    const int nc0 = wn * 32;
#pragma unroll
    for (int im = 0; im < 2; im++)
#pragma unroll
        for (int jn = 0; jn < 4; jn++) {
            int cc = nc0 + jn * 8 + 2 * (lane & 3);
            int r0 = mr + im * 16 + (lane >> 2);
            if (r0 < N)
                *(float2*)&P[(size_t)r0 * 128 + cc] =
                    make_float2(acc[im][jn][0], acc[im][jn][1]);
            int r1 = r0 + 8;
            if (r1 < N)
                *(float2*)&P[(size_t)r1 * 128 + cc] =
                    make_float2(acc[im][jn][2], acc[im][jn][3]);
        }
}

// ============================ Phase 3: reduce + tanh =======================
__global__ void __launch_bounds__(256) phase3_kernel(float* __restrict__ out, int N)
{
    int i = blockIdx.x * blockDim.x + threadIdx.x;      // float4 index
    int total = N * 32;                                  // N*128/4
    if (i >= total) return;
    size_t e = (size_t)i * 4;
    int col4 = (i & 31) * 4;

    float4 p0 = *(const float4*)&g_P[0][e];
    float4 p1 = *(const float4*)&g_P[1][e];
    float4 p2 = *(const float4*)&g_P[2][e];
    float4 z  = *(const float4*)&g_Z[e];
    float4 s  = *(const float4*)&g_S[col4];

    float4 o;
    o.x = tanhf(p0.x + p1.x + p2.x + z.x + 0.5f * s.x);
    o.y = tanhf(p0.y + p1.y + p2.y + z.y + 0.5f * s.y);
    o.z = tanhf(p0.z + p1.z + p2.z + z.z + 0.5f * s.z);
    o.w = tanhf(p0.w + p1.w + p2.w + z.w + 0.5f * s.w);
    *(float4*)&out[e] = o;
}

// ============================ Launch =======================================
extern "C" void kernel_launch(void* const* d_in, const int* in_sizes, int n_in,
                              void* d_out, int out_size)
{
    const float* adj = (const float*)d_in[0];
    const float* X   = (const float*)d_in[1];
    const float* Wn  = (const float*)d_in[2];
    const float* Ws  = (const float*)d_in[3];
    float* out = (float*)d_out;

    int N = in_sizes[1] / 128;      // 10000
    if (N > NODE_CAP) N = NODE_CAP;

    int mblocks64 = (N + 63) / 64;

    zero_kernel<<<1, 128>>>();
    phase1_kernel<<<dim3(mblocks64, 4), 256>>>(X, Wn, Ws, N);

    int smem_bytes = STAGES * (A_STAGE + B_STAGE) * (int)sizeof(float); // 53248
    cudaFuncSetAttribute(phase2_kernel,
                         cudaFuncAttributeMaxDynamicSharedMemorySize, smem_bytes);
    phase2_kernel<<<dim3(mblocks64, SPLITS), 256, smem_bytes>>>(adj, N);

    int p3blocks = (N * 32 + 255) / 256;
    phase3_kernel<<<p3blocks, 256>>>(out, N);
}

// round 11
// speedup vs baseline: 1.5816x; 1.0057x over previous
#include <cuda_runtime.h>
#include <math.h>
#include <stdint.h>

// ---------------------------------------------------------------------------
// out = tanh( adj @ (X @ Wn^T) + X @ Ws^T ),  N=10000, feature dim 128
//
// Y = X@Wn^T, Z = X@Ws^T (tiny), then out = tanh(adj@Y + Z).
// Precision (tf32 mma with fp32-grade accuracy):
//   adj@Y = (adj-0.5)@Y + 0.5*colsum(Y)
//   A side: register split  a-0.5 = a_hi(tf32,rna) + a_lo -> 2 mma passes
//   B side: Y rounded to tf32 (rna) in phase1; colsum from exact Y
// R10: CTA tile 128x128, warp tile 32x64 (4x2) -> 2x mma per issue slot,
//      STAGES=3, SPLITS=4, 2 CTAs/SM.
// ---------------------------------------------------------------------------

#define NODE_CAP 10016
#define SPLITS 4
__device__ float g_Y[NODE_CAP * 128];
__device__ float g_Z[NODE_CAP * 128];
__device__ float g_S[128];                         // colsum of exact Y
__device__ float g_P[SPLITS][NODE_CAP * 128];      // split-K partials

// ============================ helpers ======================================
__device__ __forceinline__ unsigned rna_tf32(float v)
{
    unsigned b;
    asm("cvt.rna.tf32.f32 %0, %1;" : "=r"(b) : "f"(v));
    return b;
}

__device__ __forceinline__ void split_tf32(float v, unsigned& hi, unsigned& lo)
{
    float ap = v - 0.5f;                 // center adj
    unsigned h = rna_tf32(ap);
    hi = h;
    lo = __float_as_uint(ap - __uint_as_float(h));   // residual
}

// ============================ Phase 0: zero colsum =========================
__global__ void zero_kernel() { g_S[threadIdx.x] = 0.f; }

// ============================ Phase 1 ======================================
// grid (ceil(N/64), 4), block 256. blockIdx.y: 0,1 -> Y (Wn), 2,3 -> Z (Ws).
// Y blocks: store tf32-rna-rounded Y + atomically accumulate exact colsums.
__global__ void __launch_bounds__(256) phase1_kernel(
    const float* __restrict__ X, const float* __restrict__ Wn,
    const float* __restrict__ Ws, int N)
{
    __shared__ float As[64][64];   // As[k][m]
    __shared__ float Bs[64][64];   // Bs[k][n]
    const int tid = threadIdx.x;
    const int tx = tid & 15, ty = tid >> 4;
    const int m0 = blockIdx.x * 64;
    const int nb = blockIdx.y;
    const float* __restrict__ W = (nb < 2) ? Wn : Ws;
    const int n0 = (nb & 1) * 64;

    float acc[4][4];
#pragma unroll
    for (int i = 0; i < 4; i++)
#pragma unroll
        for (int j = 0; j < 4; j++) acc[i][j] = 0.f;

    for (int kt = 0; kt < 2; kt++) {
        __syncthreads();
#pragma unroll
        for (int it = 0; it < 4; it++) {
            int e = tid + it * 256;
            int m = e & 63, kq = e >> 6;
            float4 v = make_float4(0.f, 0.f, 0.f, 0.f);
            if (m0 + m < N)
                v = *(const float4*)&X[(size_t)(m0 + m) * 128 + kt * 64 + kq * 4];
            As[kq * 4 + 0][m] = v.x; As[kq * 4 + 1][m] = v.y;
            As[kq * 4 + 2][m] = v.z; As[kq * 4 + 3][m] = v.w;
            float4 w = *(const float4*)&W[(size_t)(n0 + m) * 128 + kt * 64 + kq * 4];
            Bs[kq * 4 + 0][m] = w.x; Bs[kq * 4 + 1][m] = w.y;
            Bs[kq * 4 + 2][m] = w.z; Bs[kq * 4 + 3][m] = w.w;
        }
        __syncthreads();
#pragma unroll 8
        for (int k = 0; k < 64; k++) {
            float4 a = *(const float4*)&As[k][ty * 4];
            float4 b = *(const float4*)&Bs[k][tx * 4];
            acc[0][0] += a.x * b.x; acc[0][1] += a.x * b.y; acc[0][2] += a.x * b.z; acc[0][3] += a.x * b.w;
            acc[1][0] += a.y * b.x; acc[1][1] += a.y * b.y; acc[1][2] += a.y * b.z; acc[1][3] += a.y * b.w;
            acc[2][0] += a.z * b.x; acc[2][1] += a.z * b.y; acc[2][2] += a.z * b.z; acc[2][3] += a.z * b.w;
            acc[3][0] += a.w * b.x; acc[3][1] += a.w * b.y; acc[3][2] += a.w * b.z; acc[3][3] += a.w * b.w;
        }
    }

    const bool isY = (nb < 2);
    float* __restrict__ dst = isY ? g_Y : g_Z;
    const int colg = (nb & 1) * 64 + tx * 4;
    float csum[4] = {0.f, 0.f, 0.f, 0.f};
#pragma unroll
    for (int i = 0; i < 4; i++) {
        int r = m0 + ty * 4 + i;
        if (r < N) {
            float4 o;
            if (isY) {
#pragma unroll
                for (int j = 0; j < 4; j++) csum[j] += acc[i][j];
                o = make_float4(__uint_as_float(rna_tf32(acc[i][0])),
                                __uint_as_float(rna_tf32(acc[i][1])),
                                __uint_as_float(rna_tf32(acc[i][2])),
                                __uint_as_float(rna_tf32(acc[i][3])));
            } else {
                o = make_float4(acc[i][0], acc[i][1], acc[i][2], acc[i][3]);
            }
            *(float4*)&dst[(size_t)r * 128 + colg] = o;
        }
    }

    if (isY) {
        __syncthreads();
        float* red = &As[0][0];          // reuse as [16][64]
#pragma unroll
        for (int j = 0; j < 4; j++) red[ty * 64 + tx * 4 + j] = csum[j];
        __syncthreads();
        if (tid < 64) {
            float s = 0.f;
#pragma unroll
            for (int t = 0; t < 16; t++) s += red[t * 64 + tid];
            atomicAdd(&g_S[(nb & 1) * 64 + tid], s);
        }
    }
}

// ============================ Phase 2 ======================================
#define KC 32
#define STAGES 3
#define A_LD 36     // frag lds bank = (4r+c)%32 -> conflict-free
#define B_LD 136    // frag lds bank = (8k+n)%32 -> conflict-free
#define A_STAGE (128 * A_LD)
#define B_STAGE (32 * B_LD)

__device__ __forceinline__ void cp16(float* smem_dst, const float* gsrc, bool pred)
{
    unsigned sa = (unsigned)__cvta_generic_to_shared(smem_dst);
    int sz = pred ? 16 : 0;   // sz=0 -> zero-fill 16B
    asm volatile("cp.async.cg.shared.global [%0], [%1], 16, %2;\n"
                 :: "r"(sa), "l"(gsrc), "r"(sz));
}

__device__ __forceinline__ void issue_chunk(
    float* sA, float* sB, const float* __restrict__ adj,
    const float* __restrict__ Y, int m0, int k0, int N, int tid)
{
    // A tile: 128 rows x 32 cols = 1024 float4
#pragma unroll
    for (int it = 0; it < 4; it++) {
        int e = tid + it * 256;
        int row = e >> 3, kq = e & 7;
        int gr = m0 + row, gc = k0 + kq * 4;
        bool p = (gr < N) && (gc < N);
        const float* src = adj + (size_t)(p ? gr : 0) * (size_t)N + (p ? gc : 0);
        cp16(&sA[row * A_LD + kq * 4], src, p);
    }
    // B tile: 32 rows x 128 cols = 1024 float4
#pragma unroll
    for (int it = 0; it < 4; it++) {
        int e = tid + it * 256;
        int row = e >> 5;                  // 0..31
        int kq = e & 31;                   // 0..31 float4
        int gr = k0 + row;
        bool p = (gr < N);
        const float* src = Y + (size_t)(p ? gr : 0) * 128 + kq * 4;
        cp16(&sB[row * B_LD + kq * 4], src, p);
    }
    asm volatile("cp.async.commit_group;\n" ::);
}

__device__ __forceinline__ void mma_tf32(float* c, const unsigned* a, const unsigned* b)
{
    asm volatile(
        "mma.sync.aligned.m16n8k8.row.col.f32.tf32.tf32.f32 "
        "{%0,%1,%2,%3},{%4,%5,%6,%7},{%8,%9},{%0,%1,%2,%3};\n"
        : "+f"(c[0]), "+f"(c[1]), "+f"(c[2]), "+f"(c[3])
        : "r"(a[0]), "r"(a[1]), "r"(a[2]), "r"(a[3]), "r"(b[0]), "r"(b[1]));
}

// grid (ceil(N/128), SPLITS), block 256 (8 warps, 4x2 layout, 32x64 each).
__global__ void __launch_bounds__(256, 2) phase2_kernel(
    const float* __restrict__ adj, int N)
{
    extern __shared__ float smem[];
    float* sAb = smem;
    float* sBb = smem + STAGES * A_STAGE;

    const int tid = threadIdx.x;
    const int lane = tid & 31;
    const int warp = tid >> 5;
    const int wm = warp >> 1;  // 0..3 -> 32-row tile
    const int wn = warp & 1;   // 0..1 -> 64-col tile
    const int m0 = blockIdx.x * 128;
    const int split = blockIdx.y;

    float acc[2][8][4];
#pragma unroll
    for (int i = 0; i < 2; i++)
#pragma unroll
        for (int j = 0; j < 8; j++)
#pragma unroll
            for (int k = 0; k < 4; k++) acc[i][j][k] = 0.f;

    const int NCtot = (N + KC - 1) / KC;
    const int per = (NCtot + SPLITS - 1) / SPLITS;
    const int c_begin = split * per;
    const int c_end = min(NCtot, c_begin + per);

    for (int c = c_begin; c < c_begin + (STAGES - 1) && c < c_end; c++)
        issue_chunk(sAb + (c % STAGES) * A_STAGE, sBb + (c % STAGES) * B_STAGE,
                    adj, g_Y, m0, c * KC, N, tid);

    for (int c = c_begin; c < c_end; c++) {
        asm volatile("cp.async.wait_group %0;\n" :: "n"(STAGES - 2));
        __syncthreads();

        int nc_ = c + STAGES - 1;
        if (nc_ < c_end)
            issue_chunk(sAb + (nc_ % STAGES) * A_STAGE, sBb + (nc_ % STAGES) * B_STAGE,
                        adj, g_Y, m0, nc_ * KC, N, tid);
        else
            asm volatile("cp.async.commit_group;\n" ::);

        const float* A = sAb + (c % STAGES) * A_STAGE;
        const float* B = sBb + (c % STAGES) * B_STAGE;

#pragma unroll
        for (int ks = 0; ks < 4; ks++) {
            unsigned ahi[2][4], alo[2][4], b[8][2];
#pragma unroll
            for (int im = 0; im < 2; im++) {
                int r = wm * 32 + im * 16 + (lane >> 2);
                int cc = ks * 8 + (lane & 3);
                float v0 = A[r * A_LD + cc];
                float v1 = A[(r + 8) * A_LD + cc];
                float v2 = A[r * A_LD + cc + 4];
                float v3 = A[(r + 8) * A_LD + cc + 4];
                split_tf32(v0, ahi[im][0], alo[im][0]);
                split_tf32(v1, ahi[im][1], alo[im][1]);
                split_tf32(v2, ahi[im][2], alo[im][2]);
                split_tf32(v3, ahi[im][3], alo[im][3]);
            }
#pragma unroll
            for (int jn = 0; jn < 8; jn++) {
                int col = wn * 64 + jn * 8 + (lane >> 2);
                int rr = ks * 8 + (lane & 3);
                b[jn][0] = __float_as_uint(B[rr * B_LD + col]);   // pre-rounded tf32
                b[jn][1] = __float_as_uint(B[(rr + 4) * B_LD + col]);
            }
#pragma unroll
            for (int im = 0; im < 2; im++)
#pragma unroll
                for (int jn = 0; jn < 8; jn++) {
                    mma_tf32(acc[im][jn], ahi[im], b[jn]);   // hi pass
                    mma_tf32(acc[im][jn], alo[im], b[jn]);   // lo pass
                }
        }
    }

    // store fp32 partials
    float* __restrict__ P = g_P[split];
    const int mr = m0 + wm * 32;
    const int nc0 = wn * 64;
#pragma unroll
    for (int im = 0; im < 2; im++)
#pragma unroll
        for (int jn = 0; jn < 8; jn++) {
            int cc = nc0 + jn * 8 + 2 * (lane & 3);
            int r0 = mr + im * 16 + (lane >> 2);
            if (r0 < N)
                *(float2*)&P[(size_t)r0 * 128 + cc] =
                    make_float2(acc[im][jn][0], acc[im][jn][1]);
            int r1 = r0 + 8;
            if (r1 < N)
                *(float2*)&P[(size_t)r1 * 128 + cc] =
                    make_float2(acc[im][jn][2], acc[im][jn][3]);
        }
}

// ============================ Phase 3: reduce + tanh =======================
__global__ void __launch_bounds__(256) phase3_kernel(float* __restrict__ out, int N)
{
    int i = blockIdx.x * blockDim.x + threadIdx.x;      // float4 index
    int total = N * 32;                                  // N*128/4
    if (i >= total) return;
    size_t e = (size_t)i * 4;
    int col4 = (i & 31) * 4;

    float4 p0 = *(const float4*)&g_P[0][e];
    float4 p1 = *(const float4*)&g_P[1][e];
    float4 p2 = *(const float4*)&g_P[2][e];
    float4 p3 = *(const float4*)&g_P[3][e];
    float4 z  = *(const float4*)&g_Z[e];
    float4 s  = *(const float4*)&g_S[col4];

    float4 o;
    o.x = tanhf((p0.x + p1.x) + (p2.x + p3.x) + z.x + 0.5f * s.x);
    o.y = tanhf((p0.y + p1.y) + (p2.y + p3.y) + z.y + 0.5f * s.y);
    o.z = tanhf((p0.z + p1.z) + (p2.z + p3.z) + z.z + 0.5f * s.z);
    o.w = tanhf((p0.w + p1.w) + (p2.w + p3.w) + z.w + 0.5f * s.w);
    *(float4*)&out[e] = o;
}

// ============================ Launch =======================================
extern "C" void kernel_launch(void* const* d_in, const int* in_sizes, int n_in,
                              void* d_out, int out_size)
{
    const float* adj = (const float*)d_in[0];
    const float* X   = (const float*)d_in[1];
    const float* Wn  = (const float*)d_in[2];
    const float* Ws  = (const float*)d_in[3];
    float* out = (float*)d_out;

    int N = in_sizes[1] / 128;      // 10000
    if (N > NODE_CAP) N = NODE_CAP;

    int mblocks64 = (N + 63) / 64;
    int mblocks128 = (N + 127) / 128;

    zero_kernel<<<1, 128>>>();
    phase1_kernel<<<dim3(mblocks64, 4), 256>>>(X, Wn, Ws, N);

    int smem_bytes = STAGES * (A_STAGE + B_STAGE) * (int)sizeof(float); // 107520
    cudaFuncSetAttribute(phase2_kernel,
                         cudaFuncAttributeMaxDynamicSharedMemorySize, smem_bytes);
    phase2_kernel<<<dim3(mblocks128, SPLITS), 256, smem_bytes>>>(adj, N);

    int p3blocks = (N * 32 + 255) / 256;
    phase3_kernel<<<p3blocks, 256>>>(out, N);
}

// round 12
// speedup vs baseline: 1.7262x; 1.0914x over previous
#include <cuda_runtime.h>
#include <math.h>
#include <stdint.h>

// ---------------------------------------------------------------------------
// out = tanh( adj @ (X @ Wn^T) + X @ Ws^T ),  N=10000, feature dim 128
//
// Y = X@Wn^T, Z = X@Ws^T (tiny), then out = tanh(adj@Y + Z).
// Precision (tf32 mma with fp32-grade accuracy):
//   adj@Y = (adj-0.5)@Y + 0.5*colsum(Y)
//   A side: register split  a-0.5 = a_hi(tf32,rna) + a_lo -> 2 mma passes
//   B side: Y rounded to tf32 (rna) in phase1; colsum from exact Y
// R11: SPLITS 4 -> 3. Grid 79x3=237 <= 296 slots (2 CTAs/SM x 148) -> ONE
//      wave instead of 2 (316 vs 296 was a full second wave for 20 CTAs).
// ---------------------------------------------------------------------------

#define NODE_CAP 10016
#define SPLITS 3
__device__ float g_Y[NODE_CAP * 128];
__device__ float g_Z[NODE_CAP * 128];
__device__ float g_S[128];                         // colsum of exact Y
__device__ float g_P[SPLITS][NODE_CAP * 128];      // split-K partials

// ============================ helpers ======================================
__device__ __forceinline__ unsigned rna_tf32(float v)
{
    unsigned b;
    asm("cvt.rna.tf32.f32 %0, %1;" : "=r"(b) : "f"(v));
    return b;
}

__device__ __forceinline__ void split_tf32(float v, unsigned& hi, unsigned& lo)
{
    float ap = v - 0.5f;                 // center adj
    unsigned h = rna_tf32(ap);
    hi = h;
    lo = __float_as_uint(ap - __uint_as_float(h));   // residual
}

// ============================ Phase 0: zero colsum =========================
__global__ void zero_kernel() { g_S[threadIdx.x] = 0.f; }

// ============================ Phase 1 ======================================
// grid (ceil(N/64), 4), block 256. blockIdx.y: 0,1 -> Y (Wn), 2,3 -> Z (Ws).
// Y blocks: store tf32-rna-rounded Y + atomically accumulate exact colsums.
__global__ void __launch_bounds__(256) phase1_kernel(
    const float* __restrict__ X, const float* __restrict__ Wn,
    const float* __restrict__ Ws, int N)
{
    __shared__ float As[64][64];   // As[k][m]
    __shared__ float Bs[64][64];   // Bs[k][n]
    const int tid = threadIdx.x;
    const int tx = tid & 15, ty = tid >> 4;
    const int m0 = blockIdx.x * 64;
    const int nb = blockIdx.y;
    const float* __restrict__ W = (nb < 2) ? Wn : Ws;
    const int n0 = (nb & 1) * 64;

    float acc[4][4];
#pragma unroll
    for (int i = 0; i < 4; i++)
#pragma unroll
        for (int j = 0; j < 4; j++) acc[i][j] = 0.f;

    for (int kt = 0; kt < 2; kt++) {
        __syncthreads();
#pragma unroll
        for (int it = 0; it < 4; it++) {
            int e = tid + it * 256;
            int m = e & 63, kq = e >> 6;
            float4 v = make_float4(0.f, 0.f, 0.f, 0.f);
            if (m0 + m < N)
                v = *(const float4*)&X[(size_t)(m0 + m) * 128 + kt * 64 + kq * 4];
            As[kq * 4 + 0][m] = v.x; As[kq * 4 + 1][m] = v.y;
            As[kq * 4 + 2][m] = v.z; As[kq * 4 + 3][m] = v.w;
            float4 w = *(const float4*)&W[(size_t)(n0 + m) * 128 + kt * 64 + kq * 4];
            Bs[kq * 4 + 0][m] = w.x; Bs[kq * 4 + 1][m] = w.y;
            Bs[kq * 4 + 2][m] = w.z; Bs[kq * 4 + 3][m] = w.w;
        }
        __syncthreads();
#pragma unroll 8
        for (int k = 0; k < 64; k++) {
            float4 a = *(const float4*)&As[k][ty * 4];
            float4 b = *(const float4*)&Bs[k][tx * 4];
            acc[0][0] += a.x * b.x; acc[0][1] += a.x * b.y; acc[0][2] += a.x * b.z; acc[0][3] += a.x * b.w;
            acc[1][0] += a.y * b.x; acc[1][1] += a.y * b.y; acc[1][2] += a.y * b.z; acc[1][3] += a.y * b.w;
            acc[2][0] += a.z * b.x; acc[2][1] += a.z * b.y; acc[2][2] += a.z * b.z; acc[2][3] += a.z * b.w;
            acc[3][0] += a.w * b.x; acc[3][1] += a.w * b.y; acc[3][2] += a.w * b.z; acc[3][3] += a.w * b.w;
        }
    }

    const bool isY = (nb < 2);
    float* __restrict__ dst = isY ? g_Y : g_Z;
    const int colg = (nb & 1) * 64 + tx * 4;
    float csum[4] = {0.f, 0.f, 0.f, 0.f};
#pragma unroll
    for (int i = 0; i < 4; i++) {
        int r = m0 + ty * 4 + i;
        if (r < N) {
            float4 o;
            if (isY) {
#pragma unroll
                for (int j = 0; j < 4; j++) csum[j] += acc[i][j];
                o = make_float4(__uint_as_float(rna_tf32(acc[i][0])),
                                __uint_as_float(rna_tf32(acc[i][1])),
                                __uint_as_float(rna_tf32(acc[i][2])),
                                __uint_as_float(rna_tf32(acc[i][3])));
            } else {
                o = make_float4(acc[i][0], acc[i][1], acc[i][2], acc[i][3]);
            }
            *(float4*)&dst[(size_t)r * 128 + colg] = o;
        }
    }

    if (isY) {
        __syncthreads();
        float* red = &As[0][0];          // reuse as [16][64]
#pragma unroll
        for (int j = 0; j < 4; j++) red[ty * 64 + tx * 4 + j] = csum[j];
        __syncthreads();
        if (tid < 64) {
            float s = 0.f;
#pragma unroll
            for (int t = 0; t < 16; t++) s += red[t * 64 + tid];
            atomicAdd(&g_S[(nb & 1) * 64 + tid], s);
        }
    }
}

// ============================ Phase 2 ======================================
#define KC 32
#define STAGES 3
#define A_LD 36     // frag lds bank = (4r+c)%32 -> conflict-free
#define B_LD 136    // frag lds bank = (8k+n)%32 -> conflict-free
#define A_STAGE (128 * A_LD)
#define B_STAGE (32 * B_LD)

__device__ __forceinline__ void cp16(float* smem_dst, const float* gsrc, bool pred)
{
    unsigned sa = (unsigned)__cvta_generic_to_shared(smem_dst);
    int sz = pred ? 16 : 0;   // sz=0 -> zero-fill 16B
    asm volatile("cp.async.cg.shared.global [%0], [%1], 16, %2;\n"
                 :: "r"(sa), "l"(gsrc), "r"(sz));
}

__device__ __forceinline__ void issue_chunk(
    float* sA, float* sB, const float* __restrict__ adj,
    const float* __restrict__ Y, int m0, int k0, int N, int tid)
{
    // A tile: 128 rows x 32 cols = 1024 float4
#pragma unroll
    for (int it = 0; it < 4; it++) {
        int e = tid + it * 256;
        int row = e >> 3, kq = e & 7;
        int gr = m0 + row, gc = k0 + kq * 4;
        bool p = (gr < N) && (gc < N);
        const float* src = adj + (size_t)(p ? gr : 0) * (size_t)N + (p ? gc : 0);
        cp16(&sA[row * A_LD + kq * 4], src, p);
    }
    // B tile: 32 rows x 128 cols = 1024 float4
#pragma unroll
    for (int it = 0; it < 4; it++) {
        int e = tid + it * 256;
        int row = e >> 5;                  // 0..31
        int kq = e & 31;                   // 0..31 float4
        int gr = k0 + row;
        bool p = (gr < N);
        const float* src = Y + (size_t)(p ? gr : 0) * 128 + kq * 4;
        cp16(&sB[row * B_LD + kq * 4], src, p);
    }
    asm volatile("cp.async.commit_group;\n" ::);
}

__device__ __forceinline__ void mma_tf32(float* c, const unsigned* a, const unsigned* b)
{
    asm volatile(
        "mma.sync.aligned.m16n8k8.row.col.f32.tf32.tf32.f32 "
        "{%0,%1,%2,%3},{%4,%5,%6,%7},{%8,%9},{%0,%1,%2,%3};\n"
        : "+f"(c[0]), "+f"(c[1]), "+f"(c[2]), "+f"(c[3])
        : "r"(a[0]), "r"(a[1]), "r"(a[2]), "r"(a[3]), "r"(b[0]), "r"(b[1]));
}

// grid (ceil(N/128), SPLITS), block 256 (8 warps, 4x2 layout, 32x64 each).
__global__ void __launch_bounds__(256, 2) phase2_kernel(
    const float* __restrict__ adj, int N)
{
    extern __shared__ float smem[];
    float* sAb = smem;
    float* sBb = smem + STAGES * A_STAGE;

    const int tid = threadIdx.x;
    const int lane = tid & 31;
    const int warp = tid >> 5;
    const int wm = warp >> 1;  // 0..3 -> 32-row tile
    const int wn = warp & 1;   // 0..1 -> 64-col tile
    const int m0 = blockIdx.x * 128;
    const int split = blockIdx.y;

    float acc[2][8][4];
#pragma unroll
    for (int i = 0; i < 2; i++)
#pragma unroll
        for (int j = 0; j < 8; j++)
#pragma unroll
            for (int k = 0; k < 4; k++) acc[i][j][k] = 0.f;

    const int NCtot = (N + KC - 1) / KC;
    const int per = (NCtot + SPLITS - 1) / SPLITS;
    const int c_begin = split * per;
    const int c_end = min(NCtot, c_begin + per);

    for (int c = c_begin; c < c_begin + (STAGES - 1) && c < c_end; c++)
        issue_chunk(sAb + (c % STAGES) * A_STAGE, sBb + (c % STAGES) * B_STAGE,
                    adj, g_Y, m0, c * KC, N, tid);

    for (int c = c_begin; c < c_end; c++) {
        asm volatile("cp.async.wait_group %0;\n" :: "n"(STAGES - 2));
        __syncthreads();

        int nc_ = c + STAGES - 1;
        if (nc_ < c_end)
            issue_chunk(sAb + (nc_ % STAGES) * A_STAGE, sBb + (nc_ % STAGES) * B_STAGE,
                        adj, g_Y, m0, nc_ * KC, N, tid);
        else
            asm volatile("cp.async.commit_group;\n" ::);

        const float* A = sAb + (c % STAGES) * A_STAGE;
        const float* B = sBb + (c % STAGES) * B_STAGE;

#pragma unroll
        for (int ks = 0; ks < 4; ks++) {
            unsigned ahi[2][4], alo[2][4], b[8][2];
#pragma unroll
            for (int im = 0; im < 2; im++) {
                int r = wm * 32 + im * 16 + (lane >> 2);
                int cc = ks * 8 + (lane & 3);
                float v0 = A[r * A_LD + cc];
                float v1 = A[(r + 8) * A_LD + cc];
                float v2 = A[r * A_LD + cc + 4];
                float v3 = A[(r + 8) * A_LD + cc + 4];
                split_tf32(v0, ahi[im][0], alo[im][0]);
                split_tf32(v1, ahi[im][1], alo[im][1]);
                split_tf32(v2, ahi[im][2], alo[im][2]);
                split_tf32(v3, ahi[im][3], alo[im][3]);
            }
#pragma unroll
            for (int jn = 0; jn < 8; jn++) {
                int col = wn * 64 + jn * 8 + (lane >> 2);
                int rr = ks * 8 + (lane & 3);
                b[jn][0] = __float_as_uint(B[rr * B_LD + col]);   // pre-rounded tf32
                b[jn][1] = __float_as_uint(B[(rr + 4) * B_LD + col]);
            }
#pragma unroll
            for (int im = 0; im < 2; im++)
#pragma unroll
                for (int jn = 0; jn < 8; jn++) {
                    mma_tf32(acc[im][jn], ahi[im], b[jn]);   // hi pass
                    mma_tf32(acc[im][jn], alo[im], b[jn]);   // lo pass
                }
        }
    }

    // store fp32 partials
    float* __restrict__ P = g_P[split];
    const int mr = m0 + wm * 32;
    const int nc0 = wn * 64;
#pragma unroll
    for (int im = 0; im < 2; im++)
#pragma unroll
        for (int jn = 0; jn < 8; jn++) {
            int cc = nc0 + jn * 8 + 2 * (lane & 3);
            int r0 = mr + im * 16 + (lane >> 2);
            if (r0 < N)
                *(float2*)&P[(size_t)r0 * 128 + cc] =
                    make_float2(acc[im][jn][0], acc[im][jn][1]);
            int r1 = r0 + 8;
            if (r1 < N)
                *(float2*)&P[(size_t)r1 * 128 + cc] =
                    make_float2(acc[im][jn][2], acc[im][jn][3]);
        }
}

// ============================ Phase 3: reduce + tanh =======================
__global__ void __launch_bounds__(256) phase3_kernel(float* __restrict__ out, int N)
{
    int i = blockIdx.x * blockDim.x + threadIdx.x;      // float4 index
    int total = N * 32;                                  // N*128/4
    if (i >= total) return;
    size_t e = (size_t)i * 4;
    int col4 = (i & 31) * 4;

    float4 p0 = *(const float4*)&g_P[0][e];
    float4 p1 = *(const float4*)&g_P[1][e];
    float4 p2 = *(const float4*)&g_P[2][e];
    float4 z  = *(const float4*)&g_Z[e];
    float4 s  = *(const float4*)&g_S[col4];

    float4 o;
    o.x = tanhf(p0.x + p1.x + p2.x + z.x + 0.5f * s.x);
    o.y = tanhf(p0.y + p1.y + p2.y + z.y + 0.5f * s.y);
    o.z = tanhf(p0.z + p1.z + p2.z + z.z + 0.5f * s.z);
    o.w = tanhf(p0.w + p1.w + p2.w + z.w + 0.5f * s.w);
    *(float4*)&out[e] = o;
}

// ============================ Launch =======================================
extern "C" void kernel_launch(void* const* d_in, const int* in_sizes, int n_in,
                              void* d_out, int out_size)
{
    const float* adj = (const float*)d_in[0];
    const float* X   = (const float*)d_in[1];
    const float* Wn  = (const float*)d_in[2];
    const float* Ws  = (const float*)d_in[3];
    float* out = (float*)d_out;

    int N = in_sizes[1] / 128;      // 10000
    if (N > NODE_CAP) N = NODE_CAP;

    int mblocks64 = (N + 63) / 64;
    int mblocks128 = (N + 127) / 128;

    zero_kernel<<<1, 128>>>();
    phase1_kernel<<<dim3(mblocks64, 4), 256>>>(X, Wn, Ws, N);

    int smem_bytes = STAGES * (A_STAGE + B_STAGE) * (int)sizeof(float); // 107520
    cudaFuncSetAttribute(phase2_kernel,
                         cudaFuncAttributeMaxDynamicSharedMemorySize, smem_bytes);
    phase2_kernel<<<dim3(mblocks128, SPLITS), 256, smem_bytes>>>(adj, N);

    int p3blocks = (N * 32 + 255) / 256;
    phase3_kernel<<<p3blocks, 256>>>(out, N);
}